// round 1
// baseline (speedup 1.0000x reference)
#include <cuda_runtime.h>
#include <cstdint>
#include <math.h>

// Problem constants
#define E_DIM 1024
#define H_NUM 16
#define HD 64
#define R_RANK 16
#define T_LEN 2048
#define B_SZ 2
#define S_LEN 2048
#define M_ROWS (T_LEN * B_SZ)   // 4096
#define BH (B_SZ * H_NUM)       // 32

// Scratch (device globals: allocation-free per harness rules)
__device__ float g_weff[4][E_DIM * E_DIM];              // folded W + lb@la (q,k,v,o)
__device__ float g_q[M_ROWS * E_DIM];
__device__ float g_k[M_ROWS * E_DIM];
__device__ float g_v[M_ROWS * E_DIM];
__device__ float g_ao[M_ROWS * E_DIM];                  // attention output, (t*B+b, h*64+d)
__device__ float g_attn[(size_t)BH * T_LEN * S_LEN];    // 512 MB probability tensor

// ---------------------------------------------------------------------------
// K0: fold LoRA into weight: Weff[i][j] = w[i][j] + sum_r lb[i][r]*la[r][j]
// (SCALING = ALPHA/R = 1)
// ---------------------------------------------------------------------------
__global__ __launch_bounds__(256) void weff_kernel(const float* __restrict__ w,
                                                   const float* __restrict__ la,
                                                   const float* __restrict__ lb,
                                                   int widx) {
    int idx = blockIdx.x * 256 + threadIdx.x;    // E*E = 1,048,576 total
    int j = idx & (E_DIM - 1);
    int i = idx >> 10;
    float acc = w[idx];
#pragma unroll
    for (int r = 0; r < R_RANK; r++)
        acc += lb[i * R_RANK + r] * la[r * E_DIM + j];
    g_weff[widx][idx] = acc;
}

// ---------------------------------------------------------------------------
// K1: Y = X @ W^T + bias     (M=4096, N=1024, K=1024)
// 128x128 tile, BK=16, 256 threads, 8x8 microtile.
// ---------------------------------------------------------------------------
__global__ __launch_bounds__(256) void gemm_bias_kernel(const float* __restrict__ Xext,
                                                        const float* __restrict__ bias,
                                                        float* __restrict__ Yext,
                                                        int widx, int ysel) {
    const int M = M_ROWS, N = E_DIM, K = E_DIM;
    __shared__ float As[16][132];
    __shared__ float Bs[16][132];

    const float* __restrict__ X = Xext ? Xext : g_ao;
    const float* __restrict__ W = g_weff[widx];
    float* __restrict__ Y = (ysel == 0) ? g_q : (ysel == 1) ? g_k : (ysel == 2) ? g_v : Yext;

    const int tid = threadIdx.x;
    const int tx = tid & 15;
    const int ty = tid >> 4;
    const int bm = blockIdx.y * 128;
    const int bn = blockIdx.x * 128;

    float acc[8][8];
#pragma unroll
    for (int i = 0; i < 8; i++)
#pragma unroll
        for (int j = 0; j < 8; j++) acc[i][j] = 0.0f;

    for (int k0 = 0; k0 < K; k0 += 16) {
#pragma unroll
        for (int l = 0; l < 2; l++) {
            int f = tid * 2 + l;         // float4 index in [0,512)
            int r = f >> 2;              // row 0..127
            int c4 = f & 3;              // which float4 in the 16-wide K slab
            float4 a = *(const float4*)&X[(size_t)(bm + r) * K + k0 + c4 * 4];
            As[c4 * 4 + 0][r] = a.x; As[c4 * 4 + 1][r] = a.y;
            As[c4 * 4 + 2][r] = a.z; As[c4 * 4 + 3][r] = a.w;
            float4 w = *(const float4*)&W[(size_t)(bn + r) * K + k0 + c4 * 4];
            Bs[c4 * 4 + 0][r] = w.x; Bs[c4 * 4 + 1][r] = w.y;
            Bs[c4 * 4 + 2][r] = w.z; Bs[c4 * 4 + 3][r] = w.w;
        }
        __syncthreads();
#pragma unroll
        for (int kk = 0; kk < 16; kk++) {
            float a[8], b[8];
#pragma unroll
            for (int i = 0; i < 8; i++) a[i] = As[kk][ty * 8 + i];
#pragma unroll
            for (int j = 0; j < 8; j++) b[j] = Bs[kk][tx * 8 + j];
#pragma unroll
            for (int i = 0; i < 8; i++)
#pragma unroll
                for (int j = 0; j < 8; j++) acc[i][j] += a[i] * b[j];
        }
        __syncthreads();
    }

#pragma unroll
    for (int i = 0; i < 8; i++) {
        int row = bm + ty * 8 + i;
#pragma unroll
        for (int j = 0; j < 8; j += 4) {
            int col = bn + tx * 8 + j;
            float4 bv = *(const float4*)&bias[col];
            float4 o;
            o.x = acc[i][j + 0] + bv.x;
            o.y = acc[i][j + 1] + bv.y;
            o.z = acc[i][j + 2] + bv.z;
            o.w = acc[i][j + 3] + bv.w;
            *(float4*)&Y[(size_t)row * N + col] = o;
        }
    }
}

// ---------------------------------------------------------------------------
// K2: scores[bh][t][s] = scale * sum_d Q[t][d]*K[s][d]
// 128x128 tile, BK=32 (two slabs of hd=64), 256 threads, 8x8 microtile.
// ---------------------------------------------------------------------------
__global__ __launch_bounds__(256) void scores_kernel() {
    __shared__ float Qs[32][132];
    __shared__ float Ks[32][132];
    const int tid = threadIdx.x;
    const int tx = tid & 15;
    const int ty = tid >> 4;
    const int bh = blockIdx.z;
    const int b = bh >> 4;
    const int h = bh & 15;
    const int bt = blockIdx.y * 128;
    const int bs = blockIdx.x * 128;

    float acc[8][8];
#pragma unroll
    for (int i = 0; i < 8; i++)
#pragma unroll
        for (int j = 0; j < 8; j++) acc[i][j] = 0.0f;

    for (int k0 = 0; k0 < HD; k0 += 32) {
#pragma unroll
        for (int l = 0; l < 4; l++) {
            int f = tid * 4 + l;         // float4 index [0,1024): 128 rows x 8
            int r = f >> 3;
            int c4 = f & 7;
            float4 q = *(const float4*)&g_q[((size_t)(bt + r) * B_SZ + b) * E_DIM + h * HD + k0 + c4 * 4];
            Qs[c4 * 4 + 0][r] = q.x; Qs[c4 * 4 + 1][r] = q.y;
            Qs[c4 * 4 + 2][r] = q.z; Qs[c4 * 4 + 3][r] = q.w;
            float4 k = *(const float4*)&g_k[((size_t)(bs + r) * B_SZ + b) * E_DIM + h * HD + k0 + c4 * 4];
            Ks[c4 * 4 + 0][r] = k.x; Ks[c4 * 4 + 1][r] = k.y;
            Ks[c4 * 4 + 2][r] = k.z; Ks[c4 * 4 + 3][r] = k.w;
        }
        __syncthreads();
#pragma unroll
        for (int kk = 0; kk < 32; kk++) {
            float a[8], b2[8];
#pragma unroll
            for (int i = 0; i < 8; i++) a[i] = Qs[kk][ty * 8 + i];
#pragma unroll
            for (int j = 0; j < 8; j++) b2[j] = Ks[kk][tx * 8 + j];
#pragma unroll
            for (int i = 0; i < 8; i++)
#pragma unroll
                for (int j = 0; j < 8; j++) acc[i][j] += a[i] * b2[j];
        }
        __syncthreads();
    }

    const float scale = 0.125f;  // 1/sqrt(64)
    float* out = g_attn + (size_t)bh * T_LEN * S_LEN;
#pragma unroll
    for (int i = 0; i < 8; i++) {
        int row = bt + ty * 8 + i;
#pragma unroll
        for (int j = 0; j < 8; j += 4) {
            int col = bs + tx * 8 + j;
            float4 o;
            o.x = acc[i][j + 0] * scale;
            o.y = acc[i][j + 1] * scale;
            o.z = acc[i][j + 2] * scale;
            o.w = acc[i][j + 3] * scale;
            *(float4*)&out[(size_t)row * S_LEN + col] = o;
        }
    }
}

// ---------------------------------------------------------------------------
// K3: in-place row softmax over 2048-wide rows. One 256-thread block per row.
// ---------------------------------------------------------------------------
__global__ __launch_bounds__(256) void softmax_kernel() {
    size_t row = blockIdx.x;
    float4* p = (float4*)(g_attn + row * (size_t)S_LEN);
    const int tid = threadIdx.x;
    const int wid = tid >> 5;
    const int lane = tid & 31;

    float4 v0 = p[tid];
    float4 v1 = p[tid + 256];

    float mx = fmaxf(fmaxf(fmaxf(v0.x, v0.y), fmaxf(v0.z, v0.w)),
                     fmaxf(fmaxf(v1.x, v1.y), fmaxf(v1.z, v1.w)));
#pragma unroll
    for (int o = 16; o > 0; o >>= 1) mx = fmaxf(mx, __shfl_xor_sync(0xffffffffu, mx, o));

    __shared__ float smax[8], ssum[8];
    if (lane == 0) smax[wid] = mx;
    __syncthreads();
    float m = smax[0];
#pragma unroll
    for (int i = 1; i < 8; i++) m = fmaxf(m, smax[i]);

    v0.x = expf(v0.x - m); v0.y = expf(v0.y - m);
    v0.z = expf(v0.z - m); v0.w = expf(v0.w - m);
    v1.x = expf(v1.x - m); v1.y = expf(v1.y - m);
    v1.z = expf(v1.z - m); v1.w = expf(v1.w - m);

    float s = v0.x + v0.y + v0.z + v0.w + v1.x + v1.y + v1.z + v1.w;
#pragma unroll
    for (int o = 16; o > 0; o >>= 1) s += __shfl_xor_sync(0xffffffffu, s, o);
    if (lane == 0) ssum[wid] = s;
    __syncthreads();
    float tot = 0.0f;
#pragma unroll
    for (int i = 0; i < 8; i++) tot += ssum[i];
    float inv = 1.0f / tot;

    v0.x *= inv; v0.y *= inv; v0.z *= inv; v0.w *= inv;
    v1.x *= inv; v1.y *= inv; v1.z *= inv; v1.w *= inv;
    p[tid] = v0;
    p[tid + 256] = v1;
}

// ---------------------------------------------------------------------------
// K4: attn_w[b][t][s] = (1/16) sum_h attn[b*16+h][t][s]  -> d_out tail
// ---------------------------------------------------------------------------
__global__ __launch_bounds__(256) void attnw_kernel(float* __restrict__ out) {
    int idx = blockIdx.x * 256 + threadIdx.x;   // float4 index over (B,T,S/4) = 2,097,152
    int s4 = idx & 511;
    int t = (idx >> 9) & 2047;
    int b = idx >> 20;
    float4 acc = make_float4(0.f, 0.f, 0.f, 0.f);
#pragma unroll
    for (int h = 0; h < 16; h++) {
        const float4* pp = (const float4*)(g_attn + ((size_t)(b * 16 + h) * T_LEN + t) * S_LEN);
        float4 v = pp[s4];
        acc.x += v.x; acc.y += v.y; acc.z += v.z; acc.w += v.w;
    }
    const float c = 1.0f / 16.0f;
    float4 o = make_float4(acc.x * c, acc.y * c, acc.z * c, acc.w * c);
    ((float4*)out)[idx] = o;
}

// ---------------------------------------------------------------------------
// K5: O[bh][t][d] = sum_s P[t][s] * V[s][d]   (BM=128 t, BN=64 d full, BK=32)
// 256 threads, 8x4 microtile. Writes g_ao in (t*B+b, h*64+d) layout.
// ---------------------------------------------------------------------------
__global__ __launch_bounds__(256) void pv_kernel() {
    __shared__ float Ps[32][132];
    __shared__ float Vs[32][68];
    const int tid = threadIdx.x;
    const int tx = tid & 15;     // 16 * 4 = 64 d-cols
    const int ty = tid >> 4;     // 16 * 8 = 128 t-rows
    const int bh = blockIdx.y;
    const int b = bh >> 4;
    const int h = bh & 15;
    const int bt = blockIdx.x * 128;

    const float* __restrict__ attn_row = g_attn + (size_t)bh * T_LEN * S_LEN;

    float acc[8][4];
#pragma unroll
    for (int i = 0; i < 8; i++)
#pragma unroll
        for (int j = 0; j < 4; j++) acc[i][j] = 0.0f;

    for (int k0 = 0; k0 < S_LEN; k0 += 32) {
#pragma unroll
        for (int l = 0; l < 4; l++) {
            int f = tid * 4 + l;          // [0,1024): 128 rows x 8 float4
            int r = f >> 3;
            int c4 = f & 7;
            float4 pv = *(const float4*)&attn_row[(size_t)(bt + r) * S_LEN + k0 + c4 * 4];
            Ps[c4 * 4 + 0][r] = pv.x; Ps[c4 * 4 + 1][r] = pv.y;
            Ps[c4 * 4 + 2][r] = pv.z; Ps[c4 * 4 + 3][r] = pv.w;
        }
#pragma unroll
        for (int l = 0; l < 2; l++) {
            int f = tid * 2 + l;          // [0,512): 32 rows x 16 float4
            int r = f >> 4;
            int c4 = f & 15;
            float4 vv = *(const float4*)&g_v[((size_t)(k0 + r) * B_SZ + b) * E_DIM + h * HD + c4 * 4];
            *(float4*)&Vs[r][c4 * 4] = vv;
        }
        __syncthreads();
#pragma unroll
        for (int kk = 0; kk < 32; kk++) {
            float a[8], bb[4];
#pragma unroll
            for (int i = 0; i < 8; i++) a[i] = Ps[kk][ty * 8 + i];
#pragma unroll
            for (int j = 0; j < 4; j++) bb[j] = Vs[kk][tx * 4 + j];
#pragma unroll
            for (int i = 0; i < 8; i++)
#pragma unroll
                for (int j = 0; j < 4; j++) acc[i][j] += a[i] * bb[j];
        }
        __syncthreads();
    }

#pragma unroll
    for (int i = 0; i < 8; i++) {
        int t = bt + ty * 8 + i;
        float4 o = make_float4(acc[i][0], acc[i][1], acc[i][2], acc[i][3]);
        *(float4*)&g_ao[((size_t)t * B_SZ + b) * E_DIM + h * HD + tx * 4] = o;
    }
}

// ---------------------------------------------------------------------------
extern "C" void kernel_launch(void* const* d_in, const int* in_sizes, int n_in,
                              void* d_out, int out_size) {
    const float* query = (const float*)d_in[0];
    const float* key   = (const float*)d_in[1];
    const float* value = (const float*)d_in[2];
    const float* w[4]    = {(const float*)d_in[3],  (const float*)d_in[7],
                            (const float*)d_in[11], (const float*)d_in[15]};
    const float* bias[4] = {(const float*)d_in[4],  (const float*)d_in[8],
                            (const float*)d_in[12], (const float*)d_in[16]};
    const float* la[4]   = {(const float*)d_in[5],  (const float*)d_in[9],
                            (const float*)d_in[13], (const float*)d_in[17]};
    const float* lb[4]   = {(const float*)d_in[6],  (const float*)d_in[10],
                            (const float*)d_in[14], (const float*)d_in[18]};
    float* out = (float*)d_out;

    // Fold LoRA into effective weights
    for (int i = 0; i < 4; i++)
        weff_kernel<<<E_DIM * E_DIM / 256, 256>>>(w[i], la[i], lb[i], i);

    // Q/K/V projections
    gemm_bias_kernel<<<dim3(8, 32), 256>>>(query, bias[0], nullptr, 0, 0);
    gemm_bias_kernel<<<dim3(8, 32), 256>>>(key,   bias[1], nullptr, 1, 1);
    gemm_bias_kernel<<<dim3(8, 32), 256>>>(value, bias[2], nullptr, 2, 2);

    // Attention
    scores_kernel<<<dim3(16, 16, 32), 256>>>();
    softmax_kernel<<<BH * T_LEN, 256>>>();
    attnw_kernel<<<8192, 256>>>(out + (size_t)T_LEN * B_SZ * E_DIM);
    pv_kernel<<<dim3(16, 32), 256>>>();

    // Output projection straight into d_out (first T*B*E floats)
    gemm_bias_kernel<<<dim3(8, 32), 256>>>(nullptr, bias[3], out, 3, 3);
}

// round 5
// speedup vs baseline: 1.6432x; 1.6432x over previous
#include <cuda_runtime.h>
#include <cuda_bf16.h>
#include <cstdint>
#include <math.h>

// Problem constants
#define E_DIM 1024
#define H_NUM 16
#define HD 64
#define R_RANK 16
#define T_LEN 2048
#define B_SZ 2
#define S_LEN 2048
#define M_ROWS (T_LEN * B_SZ)   // 4096
#define BH (B_SZ * H_NUM)       // 32

// Scratch (device globals)
__device__ float g_weff[4][E_DIM * E_DIM];
__device__ float g_q[M_ROWS * E_DIM];
__device__ float g_k[M_ROWS * E_DIM];
__device__ float g_v[M_ROWS * E_DIM];
__device__ float g_vt[(size_t)BH * HD * S_LEN];       // V^T per head: [bh][d][s]
__device__ float g_ao[M_ROWS * E_DIM];
__device__ float g_attn[(size_t)BH * T_LEN * S_LEN];  // 512 MB

// ===========================================================================
// Warp-MMA helpers (sm_80+ feature set; legal at plain sm_103 PTX target)
// ===========================================================================
__device__ __forceinline__ uint32_t smem_u32(const void* p) {
    uint32_t a;
    asm("{ .reg .u64 t; cvta.to.shared.u64 t, %1; cvt.u32.u64 %0, t; }" : "=r"(a) : "l"(p));
    return a;
}

__device__ __forceinline__ void ldm_x4(uint32_t* r, uint32_t addr) {
    asm volatile("ldmatrix.sync.aligned.m8n8.x4.shared.b16 {%0,%1,%2,%3}, [%4];"
                 : "=r"(r[0]), "=r"(r[1]), "=r"(r[2]), "=r"(r[3]) : "r"(addr));
}
__device__ __forceinline__ void mma16816(float* c, const uint32_t* a, const uint32_t* b) {
    asm volatile(
        "mma.sync.aligned.m16n8k16.row.col.f32.bf16.bf16.f32 "
        "{%0,%1,%2,%3}, {%4,%5,%6,%7}, {%8,%9}, {%0,%1,%2,%3};"
        : "+f"(c[0]), "+f"(c[1]), "+f"(c[2]), "+f"(c[3])
        : "r"(a[0]), "r"(a[1]), "r"(a[2]), "r"(a[3]), "r"(b[0]), "r"(b[1]));
}

__device__ __forceinline__ unsigned pack_bf16x2(float a, float b) {
    __nv_bfloat162 t = __floats2bfloat162_rn(a, b);  // .x = a (low half)
    return reinterpret_cast<unsigned&>(t);
}

// float4 -> 4 hi bf16 (8B) + 4 lo bf16 (8B)
__device__ __forceinline__ void cvt8(__nv_bfloat16* hiP, __nv_bfloat16* loP, float4 v) {
    float hx = __bfloat162float(__float2bfloat16(v.x));
    float hy = __bfloat162float(__float2bfloat16(v.y));
    float hz = __bfloat162float(__float2bfloat16(v.z));
    float hw = __bfloat162float(__float2bfloat16(v.w));
    uint2 hi = make_uint2(pack_bf16x2(v.x, v.y), pack_bf16x2(v.z, v.w));
    uint2 lo = make_uint2(pack_bf16x2(v.x - hx, v.y - hy), pack_bf16x2(v.z - hz, v.w - hw));
    *(uint2*)hiP = hi;
    *(uint2*)loP = lo;
}

// ===========================================================================
// 3-term bf16-split warp-MMA GEMM:  C = scale * (A @ B^T) + bias
// A: [M,K] fp32 row-major (lda), B: [N,K] fp32 row-major (ldb), C: [M,N] (ldc)
// BM=128, BK=32 fp32, BN template {128, 64}. 256 threads = 8 warps (4m x 2n).
// ===========================================================================
template <int BN>
__global__ __launch_bounds__(256) void gemm_mma(
    const float* __restrict__ A, int lda, long long aBatch,
    const float* __restrict__ B, int ldb, long long bBatch,
    float* __restrict__ C, int ldc, long long cBatch,
    const float* __restrict__ bias, float scale, int K)
{
    constexpr int BM = 128;
    constexpr int SK = 40;            // bf16 elems per smem row (32 + 8 pad) = 80B
    constexpr int WN = BN / 2;        // warp tile N (64 or 32)
    constexpr int NP = WN / 16;       // 16-col pairs per warp (4 or 2)

    extern __shared__ __nv_bfloat16 sm[];
    __nv_bfloat16* Ah = sm;
    __nv_bfloat16* Al = Ah + BM * SK;
    __nv_bfloat16* Bh = Al + BM * SK;
    __nv_bfloat16* Bl = Bh + BN * SK;

    const int tid = threadIdx.x;
    const int wid = tid >> 5;
    const int lane = tid & 31;
    const int wm0 = (wid >> 1) * 32;   // warp row origin
    const int wn0 = (wid & 1) * WN;    // warp col origin
    const int z = blockIdx.z;

    A += (size_t)(blockIdx.y * BM) * lda + (size_t)z * aBatch;
    B += (size_t)(blockIdx.x * BN) * ldb + (size_t)z * bBatch;
    C += (size_t)(blockIdx.y * BM) * ldc + blockIdx.x * BN + (size_t)z * cBatch;
    if (bias) bias += blockIdx.x * BN;

    const uint32_t sb = smem_u32(sm);
    const uint32_t offAh = 0;
    const uint32_t offAl = BM * SK * 2;
    const uint32_t offBh = 2 * BM * SK * 2;
    const uint32_t offBl = offBh + BN * SK * 2;

    float acc[2][2 * NP][4];
#pragma unroll
    for (int i = 0; i < 2; i++)
#pragma unroll
        for (int j = 0; j < 2 * NP; j++)
#pragma unroll
            for (int q = 0; q < 4; q++) acc[i][j][q] = 0.0f;

    // ldmatrix per-lane addresses (element offsets within a tile, stride SK)
    // A (x4): m0..7/k0..7, m8..15/k0..7, m0..7/k8..15, m8..15/k8..15 -> a0..a3
    const int a_row = lane & 15;                    // + m-tile base
    const int a_col = (lane >> 4) << 3;             // + kk*16
    // B (x4, non-trans; smem rows = n, cols = k):
    //   mat0 = n0..7/k0..7 (b0 of n-low mma), mat1 = n0..7/k8..15 (b1 of n-low),
    //   mat2 = n8..15/k0..7, mat3 = n8..15/k8..15
    const int b_row = (lane & 7) + ((lane >> 4) << 3);
    const int b_col = ((lane >> 3) & 1) << 3;       // + kk*16

    for (int k0 = 0; k0 < K; k0 += 32) {
        // --- load + split A tile (128 x 32) ---
#pragma unroll
        for (int l = 0; l < 4; l++) {
            int f = tid + l * 256;       // float4 index, 1024 total
            int r = f >> 3, c4 = f & 7;
            float4 v = *(const float4*)(A + (size_t)r * lda + k0 + c4 * 4);
            cvt8(Ah + r * SK + c4 * 4, Al + r * SK + c4 * 4, v);
        }
        // --- load + split B tile (BN x 32) ---
#pragma unroll
        for (int l = 0; l < BN / 32; l++) {
            int f = tid + l * 256;
            int r = f >> 3, c4 = f & 7;
            float4 v = *(const float4*)(B + (size_t)r * ldb + k0 + c4 * 4);
            cvt8(Bh + r * SK + c4 * 4, Bl + r * SK + c4 * 4, v);
        }
        __syncthreads();

#pragma unroll
        for (int kk = 0; kk < 2; kk++) {
            uint32_t ah[2][4], al[2][4];
#pragma unroll
            for (int mi = 0; mi < 2; mi++) {
                uint32_t ea = ((wm0 + mi * 16 + a_row) * SK + kk * 16 + a_col) * 2;
                ldm_x4(ah[mi], sb + offAh + ea);
                ldm_x4(al[mi], sb + offAl + ea);
            }
#pragma unroll
            for (int pi = 0; pi < NP; pi++) {
                uint32_t bh4[4], bl4[4];
                uint32_t eb = ((wn0 + pi * 16 + b_row) * SK + kk * 16 + b_col) * 2;
                ldm_x4(bh4, sb + offBh + eb);
                ldm_x4(bl4, sb + offBl + eb);
                uint32_t bh0[2] = {bh4[0], bh4[1]}, bh1[2] = {bh4[2], bh4[3]};
                uint32_t bl0[2] = {bl4[0], bl4[1]}, bl1[2] = {bl4[2], bl4[3]};
#pragma unroll
                for (int mi = 0; mi < 2; mi++) {
                    mma16816(acc[mi][2 * pi + 0], ah[mi], bh0);
                    mma16816(acc[mi][2 * pi + 1], ah[mi], bh1);
                    mma16816(acc[mi][2 * pi + 0], ah[mi], bl0);
                    mma16816(acc[mi][2 * pi + 1], ah[mi], bl1);
                    mma16816(acc[mi][2 * pi + 0], al[mi], bh0);
                    mma16816(acc[mi][2 * pi + 1], al[mi], bh1);
                }
            }
        }
        __syncthreads();
    }

    // --- epilogue ---
    const int er = lane >> 2;
    const int ec = (lane & 3) * 2;
#pragma unroll
    for (int mi = 0; mi < 2; mi++) {
#pragma unroll
        for (int fi = 0; fi < 2 * NP; fi++) {
            int row = wm0 + mi * 16 + er;
            int col = wn0 + fi * 8 + ec;
            float bx = 0.f, by = 0.f;
            if (bias) { bx = bias[col]; by = bias[col + 1]; }
            float2 o0 = make_float2(acc[mi][fi][0] * scale + bx,
                                    acc[mi][fi][1] * scale + by);
            float2 o1 = make_float2(acc[mi][fi][2] * scale + bx,
                                    acc[mi][fi][3] * scale + by);
            *(float2*)(C + (size_t)row * ldc + col) = o0;
            *(float2*)(C + (size_t)(row + 8) * ldc + col) = o1;
        }
    }
}

// ---------------------------------------------------------------------------
// K0: fold LoRA into weight (SCALING = 1)
// ---------------------------------------------------------------------------
__global__ __launch_bounds__(256) void weff_kernel(const float* __restrict__ w,
                                                   const float* __restrict__ la,
                                                   const float* __restrict__ lb,
                                                   int widx) {
    int idx = blockIdx.x * 256 + threadIdx.x;
    int j = idx & (E_DIM - 1);
    int i = idx >> 10;
    float acc = w[idx];
#pragma unroll
    for (int r = 0; r < R_RANK; r++)
        acc += lb[i * R_RANK + r] * la[r * E_DIM + j];
    g_weff[widx][idx] = acc;
}

// ---------------------------------------------------------------------------
// Transpose V into per-head V^T: g_vt[bh][d][s] = g_v[(s*B+b)*E + h*64 + d]
// ---------------------------------------------------------------------------
__global__ void vt_kernel() {
    __shared__ float t[32][33];
    const int z = blockIdx.z;
    const int b = z >> 4, h = z & 15;
    const int s0 = blockIdx.x * 32;
    const int d0 = blockIdx.y * 32;
    const int tx = threadIdx.x, ty = threadIdx.y;  // 32 x 8
#pragma unroll
    for (int i = 0; i < 4; i++) {
        int s = s0 + ty + i * 8;
        t[ty + i * 8][tx] = g_v[((size_t)s * B_SZ + b) * E_DIM + h * HD + d0 + tx];
    }
    __syncthreads();
#pragma unroll
    for (int i = 0; i < 4; i++) {
        int d = d0 + ty + i * 8;
        g_vt[((size_t)z * HD + d) * S_LEN + s0 + tx] = t[tx][ty + i * 8];
    }
}

// ---------------------------------------------------------------------------
// K3: in-place row softmax over 2048-wide rows.
// ---------------------------------------------------------------------------
__global__ __launch_bounds__(256) void softmax_kernel() {
    size_t row = blockIdx.x;
    float4* p = (float4*)(g_attn + row * (size_t)S_LEN);
    const int tid = threadIdx.x;
    const int wid = tid >> 5;
    const int lane = tid & 31;

    float4 v0 = p[tid];
    float4 v1 = p[tid + 256];

    float mx = fmaxf(fmaxf(fmaxf(v0.x, v0.y), fmaxf(v0.z, v0.w)),
                     fmaxf(fmaxf(v1.x, v1.y), fmaxf(v1.z, v1.w)));
#pragma unroll
    for (int o = 16; o > 0; o >>= 1) mx = fmaxf(mx, __shfl_xor_sync(0xffffffffu, mx, o));

    __shared__ float smax[8], ssum[8];
    if (lane == 0) smax[wid] = mx;
    __syncthreads();
    float m = smax[0];
#pragma unroll
    for (int i = 1; i < 8; i++) m = fmaxf(m, smax[i]);

    v0.x = expf(v0.x - m); v0.y = expf(v0.y - m);
    v0.z = expf(v0.z - m); v0.w = expf(v0.w - m);
    v1.x = expf(v1.x - m); v1.y = expf(v1.y - m);
    v1.z = expf(v1.z - m); v1.w = expf(v1.w - m);

    float s = v0.x + v0.y + v0.z + v0.w + v1.x + v1.y + v1.z + v1.w;
#pragma unroll
    for (int o = 16; o > 0; o >>= 1) s += __shfl_xor_sync(0xffffffffu, s, o);
    if (lane == 0) ssum[wid] = s;
    __syncthreads();
    float tot = 0.0f;
#pragma unroll
    for (int i = 0; i < 8; i++) tot += ssum[i];
    float inv = 1.0f / tot;

    v0.x *= inv; v0.y *= inv; v0.z *= inv; v0.w *= inv;
    v1.x *= inv; v1.y *= inv; v1.z *= inv; v1.w *= inv;
    p[tid] = v0;
    p[tid + 256] = v1;
}

// ---------------------------------------------------------------------------
// K4: attn_w[b][t][s] = mean_h attn
// ---------------------------------------------------------------------------
__global__ __launch_bounds__(256) void attnw_kernel(float* __restrict__ out) {
    int idx = blockIdx.x * 256 + threadIdx.x;
    int s4 = idx & 511;
    int t = (idx >> 9) & 2047;
    int b = idx >> 20;
    float4 acc = make_float4(0.f, 0.f, 0.f, 0.f);
#pragma unroll
    for (int h = 0; h < 16; h++) {
        const float4* pp = (const float4*)(g_attn + ((size_t)(b * 16 + h) * T_LEN + t) * S_LEN);
        float4 v = pp[s4];
        acc.x += v.x; acc.y += v.y; acc.z += v.z; acc.w += v.w;
    }
    const float c = 1.0f / 16.0f;
    ((float4*)out)[idx] = make_float4(acc.x * c, acc.y * c, acc.z * c, acc.w * c);
}

// ---------------------------------------------------------------------------
extern "C" void kernel_launch(void* const* d_in, const int* in_sizes, int n_in,
                              void* d_out, int out_size) {
    const float* query = (const float*)d_in[0];
    const float* key   = (const float*)d_in[1];
    const float* value = (const float*)d_in[2];
    const float* w[4]    = {(const float*)d_in[3],  (const float*)d_in[7],
                            (const float*)d_in[11], (const float*)d_in[15]};
    const float* bias[4] = {(const float*)d_in[4],  (const float*)d_in[8],
                            (const float*)d_in[12], (const float*)d_in[16]};
    const float* la[4]   = {(const float*)d_in[5],  (const float*)d_in[9],
                            (const float*)d_in[13], (const float*)d_in[17]};
    const float* lb[4]   = {(const float*)d_in[6],  (const float*)d_in[10],
                            (const float*)d_in[14], (const float*)d_in[18]};
    float* out = (float*)d_out;

    float *p_weff, *p_q, *p_k, *p_v, *p_vt, *p_ao, *p_attn;
    cudaGetSymbolAddress((void**)&p_weff, g_weff);
    cudaGetSymbolAddress((void**)&p_q, g_q);
    cudaGetSymbolAddress((void**)&p_k, g_k);
    cudaGetSymbolAddress((void**)&p_v, g_v);
    cudaGetSymbolAddress((void**)&p_vt, g_vt);
    cudaGetSymbolAddress((void**)&p_ao, g_ao);
    cudaGetSymbolAddress((void**)&p_attn, g_attn);

    // smem: (2*128*40 + 2*BN*40) bf16
    const int SMEM128 = (2 * 128 * 40 + 2 * 128 * 40) * 2;  // 40960
    const int SMEM64  = (2 * 128 * 40 + 2 * 64 * 40) * 2;   // 30720

    // Fold LoRA into effective weights
    for (int i = 0; i < 4; i++)
        weff_kernel<<<E_DIM * E_DIM / 256, 256>>>(w[i], la[i], lb[i], i);

    // Q/K/V projections
    gemm_mma<128><<<dim3(8, 32, 1), 256, SMEM128>>>(
        query, E_DIM, 0, p_weff + 0 * (size_t)E_DIM * E_DIM, E_DIM, 0,
        p_q, E_DIM, 0, bias[0], 1.0f, E_DIM);
    gemm_mma<128><<<dim3(8, 32, 1), 256, SMEM128>>>(
        key, E_DIM, 0, p_weff + 1 * (size_t)E_DIM * E_DIM, E_DIM, 0,
        p_k, E_DIM, 0, bias[1], 1.0f, E_DIM);
    gemm_mma<128><<<dim3(8, 32, 1), 256, SMEM128>>>(
        value, E_DIM, 0, p_weff + 2 * (size_t)E_DIM * E_DIM, E_DIM, 0,
        p_v, E_DIM, 0, bias[2], 1.0f, E_DIM);

    // V^T for the PV GEMM
    vt_kernel<<<dim3(S_LEN / 32, HD / 32, BH), dim3(32, 8)>>>();

    // scores = 0.125 * Q K^T  (per head; batch offset 64*z into q/k)
    gemm_mma<128><<<dim3(16, 16, 32), 256, SMEM128>>>(
        p_q, 2048, 64, p_k, 2048, 64,
        p_attn, S_LEN, (long long)T_LEN * S_LEN, nullptr, 0.125f, HD);

    softmax_kernel<<<BH * T_LEN, 256>>>();
    attnw_kernel<<<8192, 256>>>(out + (size_t)T_LEN * B_SZ * E_DIM);

    // O_head = P @ V  (B = V^T rows, K-major)
    gemm_mma<64><<<dim3(1, 16, 32), 256, SMEM64>>>(
        p_attn, S_LEN, (long long)T_LEN * S_LEN,
        p_vt, S_LEN, (long long)HD * S_LEN,
        p_ao, 2048, 64, nullptr, 1.0f, S_LEN);

    // Output projection straight into d_out
    gemm_mma<128><<<dim3(8, 32, 1), 256, SMEM128>>>(
        p_ao, E_DIM, 0, p_weff + 3 * (size_t)E_DIM * E_DIM, E_DIM, 0,
        out, E_DIM, 0, bias[3], 1.0f, E_DIM);
}

// round 6
// speedup vs baseline: 2.3609x; 1.4368x over previous
#include <cuda_runtime.h>
#include <cuda_bf16.h>
#include <cstdint>
#include <math.h>

// Problem constants
#define E_DIM 1024
#define H_NUM 16
#define HD 64
#define R_RANK 16
#define T_LEN 2048
#define B_SZ 2
#define S_LEN 2048
#define M_ROWS (T_LEN * B_SZ)   // 4096
#define BH (B_SZ * H_NUM)       // 32

// ---------------------------------------------------------------------------
// Persistent scratch (device globals) — all GEMM operands pre-split hi/lo bf16
// ---------------------------------------------------------------------------
__device__ __align__(16) __nv_bfloat16 g_whi[4][E_DIM * E_DIM];
__device__ __align__(16) __nv_bfloat16 g_wlo[4][E_DIM * E_DIM];
__device__ __align__(16) __nv_bfloat16 g_ihi[3][M_ROWS * E_DIM];
__device__ __align__(16) __nv_bfloat16 g_ilo[3][M_ROWS * E_DIM];
__device__ __align__(16) __nv_bfloat16 g_qhi[M_ROWS * E_DIM];
__device__ __align__(16) __nv_bfloat16 g_qlo[M_ROWS * E_DIM];
__device__ __align__(16) __nv_bfloat16 g_khi[M_ROWS * E_DIM];
__device__ __align__(16) __nv_bfloat16 g_klo[M_ROWS * E_DIM];
__device__ float g_v[M_ROWS * E_DIM];
__device__ __align__(16) __nv_bfloat16 g_vthi[(size_t)BH * HD * S_LEN];
__device__ __align__(16) __nv_bfloat16 g_vtlo[(size_t)BH * HD * S_LEN];
__device__ __align__(16) __nv_bfloat16 g_aohi[M_ROWS * E_DIM];
__device__ __align__(16) __nv_bfloat16 g_aolo[M_ROWS * E_DIM];
__device__ float g_attn[(size_t)BH * T_LEN * S_LEN];           // 512 MB scores
__device__ __align__(16) __nv_bfloat16 g_phi[(size_t)BH * T_LEN * S_LEN];
__device__ __align__(16) __nv_bfloat16 g_plo[(size_t)BH * T_LEN * S_LEN];

// ===========================================================================
// Helpers
// ===========================================================================
__device__ __forceinline__ uint32_t smem_u32(const void* p) {
    uint32_t a;
    asm("{ .reg .u64 t; cvta.to.shared.u64 t, %1; cvt.u32.u64 %0, t; }" : "=r"(a) : "l"(p));
    return a;
}
__device__ __forceinline__ void ldm_x4(uint32_t* r, uint32_t addr) {
    asm volatile("ldmatrix.sync.aligned.m8n8.x4.shared.b16 {%0,%1,%2,%3}, [%4];"
                 : "=r"(r[0]), "=r"(r[1]), "=r"(r[2]), "=r"(r[3]) : "r"(addr));
}
__device__ __forceinline__ void mma16816(float* c, const uint32_t* a, const uint32_t* b) {
    asm volatile(
        "mma.sync.aligned.m16n8k16.row.col.f32.bf16.bf16.f32 "
        "{%0,%1,%2,%3}, {%4,%5,%6,%7}, {%8,%9}, {%0,%1,%2,%3};"
        : "+f"(c[0]), "+f"(c[1]), "+f"(c[2]), "+f"(c[3])
        : "r"(a[0]), "r"(a[1]), "r"(a[2]), "r"(a[3]), "r"(b[0]), "r"(b[1]));
}
__device__ __forceinline__ unsigned pack_bf16x2(float a, float b) {
    __nv_bfloat162 t = __floats2bfloat162_rn(a, b);
    return reinterpret_cast<unsigned&>(t);
}
__device__ __forceinline__ void cp16(uint32_t s, const __nv_bfloat16* g) {
    asm volatile("cp.async.cg.shared.global [%0], [%1], 16;"
                 :: "r"(s), "l"(__cvta_generic_to_global(g)));
}
#define CP_COMMIT() asm volatile("cp.async.commit_group;" ::: "memory")
#define CP_WAIT0()  asm volatile("cp.async.wait_group 0;" ::: "memory")
#define CP_WAIT1()  asm volatile("cp.async.wait_group 1;" ::: "memory")

// split fp32 -> hi/lo bf16
__device__ __forceinline__ void split1(float y, __nv_bfloat16& h, __nv_bfloat16& l) {
    h = __float2bfloat16(y);
    l = __float2bfloat16(y - __bfloat162float(h));
}

// ===========================================================================
// Pair-input 3-term GEMM:  C = scale * (A @ B^T) + bias
// A,B given as hi/lo bf16 tensors; A:[M,K](lda) row-major, B:[N,K](ldb).
// BM=128, BK=32, BN in {128,64}. 256 threads = 8 warps (4m x 2n).
// OUTMODE 0: fp32 C.  OUTMODE 1: hi/lo bf16 pair C.
// cp.async 2-stage double buffer.
// ===========================================================================
template <int BN, int OUTMODE>
__global__ __launch_bounds__(256) void gemm_pair(
    const __nv_bfloat16* __restrict__ Ahi, const __nv_bfloat16* __restrict__ Alo,
    int lda, long long aBatch,
    const __nv_bfloat16* __restrict__ Bhi, const __nv_bfloat16* __restrict__ Blo,
    int ldb, long long bBatch,
    float* __restrict__ Cf,
    __nv_bfloat16* __restrict__ Chi, __nv_bfloat16* __restrict__ Clo,
    int ldc, long long cBatch,
    const float* __restrict__ bias, float scale, int K)
{
    constexpr int BM = 128;
    constexpr int SK = 40;                 // padded row: 32 bf16 + 8 pad = 80 B
    constexpr int WN = BN / 2;
    constexpr int NP = WN / 16;
    constexpr int ATILE = BM * SK;         // elems (per hi or lo)
    constexpr int BTILE = BN * SK;
    constexpr int STAGE = 2 * ATILE + 2 * BTILE;

    extern __shared__ __nv_bfloat16 sm[];

    const int tid = threadIdx.x;
    const int wid = tid >> 5;
    const int lane = tid & 31;
    const int wm0 = (wid >> 1) * 32;
    const int wn0 = (wid & 1) * WN;
    const int z = blockIdx.z;

    Ahi += (size_t)(blockIdx.y * BM) * lda + (size_t)z * aBatch;
    Alo += (size_t)(blockIdx.y * BM) * lda + (size_t)z * aBatch;
    Bhi += (size_t)(blockIdx.x * BN) * ldb + (size_t)z * bBatch;
    Blo += (size_t)(blockIdx.x * BN) * ldb + (size_t)z * bBatch;
    const size_t cOff = (size_t)(blockIdx.y * BM) * ldc + blockIdx.x * BN + (size_t)z * cBatch;
    if (bias) bias += blockIdx.x * BN;

    const uint32_t sb = smem_u32(sm);

    float acc[2][2 * NP][4];
#pragma unroll
    for (int i = 0; i < 2; i++)
#pragma unroll
        for (int j = 0; j < 2 * NP; j++)
#pragma unroll
            for (int q = 0; q < 4; q++) acc[i][j][q] = 0.0f;

    // ldmatrix per-lane addressing (element units, row stride SK)
    const int a_row = lane & 15;
    const int a_col = (lane >> 4) << 3;
    const int b_row = (lane & 7) + ((lane >> 4) << 3);
    const int b_col = ((lane >> 3) & 1) << 3;

    const int nch = K >> 5;

    // stage loader: tiles packed [Ah | Al | Bh | Bl], 80B rows, 16B chunks
    auto load_stage = [&](int it, int st) {
        const uint32_t s0 = sb + st * (STAGE * 2);
        const int k0 = it * 32;
#pragma unroll
        for (int l = 0; l < 2; l++) {                 // A: 512 chunks/tile, 2/thread
            int idx = tid + l * 256;
            int r = idx >> 2, c = idx & 3;
            size_t g = (size_t)r * lda + k0 + c * 8;
            uint32_t so = (uint32_t)(r * SK + c * 8) * 2;
            cp16(s0 + so, Ahi + g);
            cp16(s0 + ATILE * 2 + so, Alo + g);
        }
#pragma unroll
        for (int l = 0; l < BN / 64; l++) {           // B: BN*4 chunks/tile
            int idx = tid + l * 256;
            int r = idx >> 2, c = idx & 3;
            size_t g = (size_t)r * ldb + k0 + c * 8;
            uint32_t so = (uint32_t)(r * SK + c * 8) * 2;
            cp16(s0 + 2 * ATILE * 2 + so, Bhi + g);
            cp16(s0 + (2 * ATILE + BTILE) * 2 + so, Blo + g);
        }
    };

    load_stage(0, 0);
    CP_COMMIT();

    for (int it = 0; it < nch; ++it) {
        const int st = it & 1;
        if (it + 1 < nch) { load_stage(it + 1, st ^ 1); CP_COMMIT(); CP_WAIT1(); }
        else              { CP_WAIT0(); }
        __syncthreads();

        const uint32_t offAh = sb + st * (STAGE * 2);
        const uint32_t offAl = offAh + ATILE * 2;
        const uint32_t offBh = offAl + ATILE * 2;
        const uint32_t offBl = offBh + BTILE * 2;

#pragma unroll
        for (int kk = 0; kk < 2; kk++) {
            uint32_t ah[2][4], al[2][4];
#pragma unroll
            for (int mi = 0; mi < 2; mi++) {
                uint32_t ea = ((wm0 + mi * 16 + a_row) * SK + kk * 16 + a_col) * 2;
                ldm_x4(ah[mi], offAh + ea);
                ldm_x4(al[mi], offAl + ea);
            }
#pragma unroll
            for (int pi = 0; pi < NP; pi++) {
                uint32_t bh4[4], bl4[4];
                uint32_t eb = ((wn0 + pi * 16 + b_row) * SK + kk * 16 + b_col) * 2;
                ldm_x4(bh4, offBh + eb);
                ldm_x4(bl4, offBl + eb);
                uint32_t bh0[2] = {bh4[0], bh4[1]}, bh1[2] = {bh4[2], bh4[3]};
                uint32_t bl0[2] = {bl4[0], bl4[1]}, bl1[2] = {bl4[2], bl4[3]};
#pragma unroll
                for (int mi = 0; mi < 2; mi++) {
                    mma16816(acc[mi][2 * pi + 0], ah[mi], bh0);
                    mma16816(acc[mi][2 * pi + 1], ah[mi], bh1);
                    mma16816(acc[mi][2 * pi + 0], ah[mi], bl0);
                    mma16816(acc[mi][2 * pi + 1], ah[mi], bl1);
                    mma16816(acc[mi][2 * pi + 0], al[mi], bh0);
                    mma16816(acc[mi][2 * pi + 1], al[mi], bh1);
                }
            }
        }
        __syncthreads();
    }

    // --- epilogue ---
    const int er = lane >> 2;
    const int ec = (lane & 3) * 2;
#pragma unroll
    for (int mi = 0; mi < 2; mi++) {
#pragma unroll
        for (int fi = 0; fi < 2 * NP; fi++) {
            int row = wm0 + mi * 16 + er;
            int col = wn0 + fi * 8 + ec;
            float bx = 0.f, by = 0.f;
            if (bias) { bx = bias[col]; by = bias[col + 1]; }
            float y0 = acc[mi][fi][0] * scale + bx;
            float y1 = acc[mi][fi][1] * scale + by;
            float y2 = acc[mi][fi][2] * scale + bx;
            float y3 = acc[mi][fi][3] * scale + by;
            size_t o0 = cOff + (size_t)row * ldc + col;
            size_t o1 = cOff + (size_t)(row + 8) * ldc + col;
            if (OUTMODE == 0) {
                *(float2*)(Cf + o0) = make_float2(y0, y1);
                *(float2*)(Cf + o1) = make_float2(y2, y3);
            } else {
                __nv_bfloat16 h0, l0, h1, l1, h2, l2, h3, l3;
                split1(y0, h0, l0); split1(y1, h1, l1);
                split1(y2, h2, l2); split1(y3, h3, l3);
                *(unsigned*)(Chi + o0) = pack_bf16x2(__bfloat162float(h0), __bfloat162float(h1));
                *(unsigned*)(Clo + o0) = pack_bf16x2(__bfloat162float(l0), __bfloat162float(l1));
                *(unsigned*)(Chi + o1) = pack_bf16x2(__bfloat162float(h2), __bfloat162float(h3));
                *(unsigned*)(Clo + o1) = pack_bf16x2(__bfloat162float(l2), __bfloat162float(l3));
            }
        }
    }
}

// ---------------------------------------------------------------------------
// K0: fold LoRA into weight (SCALING = 1), output hi/lo bf16 pair
// ---------------------------------------------------------------------------
__global__ __launch_bounds__(256) void weff_kernel(const float* __restrict__ w,
                                                   const float* __restrict__ la,
                                                   const float* __restrict__ lb,
                                                   int widx) {
    int idx = blockIdx.x * 256 + threadIdx.x;
    int j = idx & (E_DIM - 1);
    int i = idx >> 10;
    float acc = w[idx];
#pragma unroll
    for (int r = 0; r < R_RANK; r++)
        acc += lb[i * R_RANK + r] * la[r * E_DIM + j];
    __nv_bfloat16 h, l;
    split1(acc, h, l);
    g_whi[widx][idx] = h;
    g_wlo[widx][idx] = l;
}

// ---------------------------------------------------------------------------
// Input fp32 -> hi/lo bf16 pair (float4-granular)
// ---------------------------------------------------------------------------
__global__ __launch_bounds__(256) void cvt_in_kernel(const float* __restrict__ in, int which) {
    int i = blockIdx.x * 256 + threadIdx.x;          // float4 index over 4M/4 = 1M
    float4 v = ((const float4*)in)[i];
    __nv_bfloat16 hx, lx, hy, ly, hz, lz, hw, lw;
    split1(v.x, hx, lx); split1(v.y, hy, ly);
    split1(v.z, hz, lz); split1(v.w, hw, lw);
    uint2 hi = make_uint2(pack_bf16x2(__bfloat162float(hx), __bfloat162float(hy)),
                          pack_bf16x2(__bfloat162float(hz), __bfloat162float(hw)));
    uint2 lo = make_uint2(pack_bf16x2(__bfloat162float(lx), __bfloat162float(ly)),
                          pack_bf16x2(__bfloat162float(lz), __bfloat162float(lw)));
    ((uint2*)g_ihi[which])[i] = hi;
    ((uint2*)g_ilo[which])[i] = lo;
}

// ---------------------------------------------------------------------------
// Transpose V -> per-head V^T hi/lo: vt[bh][d][s]
// ---------------------------------------------------------------------------
__global__ void vt_kernel() {
    __shared__ float t[32][33];
    const int z = blockIdx.z;
    const int b = z >> 4, h = z & 15;
    const int s0 = blockIdx.x * 32;
    const int d0 = blockIdx.y * 32;
    const int tx = threadIdx.x, ty = threadIdx.y;  // 32 x 8
#pragma unroll
    for (int i = 0; i < 4; i++) {
        int s = s0 + ty + i * 8;
        t[ty + i * 8][tx] = g_v[((size_t)s * B_SZ + b) * E_DIM + h * HD + d0 + tx];
    }
    __syncthreads();
#pragma unroll
    for (int i = 0; i < 4; i++) {
        int d = d0 + ty + i * 8;
        float x = t[tx][ty + i * 8];
        __nv_bfloat16 hh, ll;
        split1(x, hh, ll);
        size_t o = ((size_t)z * HD + d) * S_LEN + s0 + tx;
        g_vthi[o] = hh;
        g_vtlo[o] = ll;
    }
}

// ---------------------------------------------------------------------------
// Fused softmax (per-row) + head-mean. One block per (b, t).
// Reads fp32 scores; writes P as hi/lo bf16 pair; writes mean row to out tail.
// ---------------------------------------------------------------------------
__global__ __launch_bounds__(256) void softmax_mean_kernel(float* __restrict__ outMean) {
    const int bt = blockIdx.x;                 // b*2048 + t
    const int b = bt >> 11, t = bt & 2047;
    const int tid = threadIdx.x;
    const int wid = tid >> 5;
    const int lane = tid & 31;

    __shared__ float smax[8], ssum[8];
    float macc0x = 0.f, macc0y = 0.f, macc0z = 0.f, macc0w = 0.f;
    float macc1x = 0.f, macc1y = 0.f, macc1z = 0.f, macc1w = 0.f;

    for (int h = 0; h < 16; h++) {
        const size_t rowOff = ((size_t)(b * 16 + h) * T_LEN + t) * S_LEN;
        const float4* p = (const float4*)(g_attn + rowOff);
        float4 v0 = p[tid];
        float4 v1 = p[tid + 256];

        float mx = fmaxf(fmaxf(fmaxf(v0.x, v0.y), fmaxf(v0.z, v0.w)),
                         fmaxf(fmaxf(v1.x, v1.y), fmaxf(v1.z, v1.w)));
#pragma unroll
        for (int o = 16; o > 0; o >>= 1) mx = fmaxf(mx, __shfl_xor_sync(0xffffffffu, mx, o));
        if (lane == 0) smax[wid] = mx;
        __syncthreads();
        float m = smax[0];
#pragma unroll
        for (int i = 1; i < 8; i++) m = fmaxf(m, smax[i]);

        v0.x = expf(v0.x - m); v0.y = expf(v0.y - m);
        v0.z = expf(v0.z - m); v0.w = expf(v0.w - m);
        v1.x = expf(v1.x - m); v1.y = expf(v1.y - m);
        v1.z = expf(v1.z - m); v1.w = expf(v1.w - m);

        float s = v0.x + v0.y + v0.z + v0.w + v1.x + v1.y + v1.z + v1.w;
#pragma unroll
        for (int o = 16; o > 0; o >>= 1) s += __shfl_xor_sync(0xffffffffu, s, o);
        if (lane == 0) ssum[wid] = s;
        __syncthreads();
        float tot = 0.0f;
#pragma unroll
        for (int i = 0; i < 8; i++) tot += ssum[i];
        float inv = 1.0f / tot;

        v0.x *= inv; v0.y *= inv; v0.z *= inv; v0.w *= inv;
        v1.x *= inv; v1.y *= inv; v1.z *= inv; v1.w *= inv;

        // write P pair
        __nv_bfloat16 hx, lx, hy, ly, hz, lz, hw, lw;
        split1(v0.x, hx, lx); split1(v0.y, hy, ly);
        split1(v0.z, hz, lz); split1(v0.w, hw, lw);
        uint2 hi = make_uint2(pack_bf16x2(__bfloat162float(hx), __bfloat162float(hy)),
                              pack_bf16x2(__bfloat162float(hz), __bfloat162float(hw)));
        uint2 lo = make_uint2(pack_bf16x2(__bfloat162float(lx), __bfloat162float(ly)),
                              pack_bf16x2(__bfloat162float(lz), __bfloat162float(lw)));
        ((uint2*)(g_phi + rowOff))[tid] = hi;
        ((uint2*)(g_plo + rowOff))[tid] = lo;
        split1(v1.x, hx, lx); split1(v1.y, hy, ly);
        split1(v1.z, hz, lz); split1(v1.w, hw, lw);
        hi = make_uint2(pack_bf16x2(__bfloat162float(hx), __bfloat162float(hy)),
                        pack_bf16x2(__bfloat162float(hz), __bfloat162float(hw)));
        lo = make_uint2(pack_bf16x2(__bfloat162float(lx), __bfloat162float(ly)),
                        pack_bf16x2(__bfloat162float(lz), __bfloat162float(lw)));
        ((uint2*)(g_phi + rowOff))[tid + 256] = hi;
        ((uint2*)(g_plo + rowOff))[tid + 256] = lo;

        macc0x += v0.x; macc0y += v0.y; macc0z += v0.z; macc0w += v0.w;
        macc1x += v1.x; macc1y += v1.y; macc1z += v1.z; macc1w += v1.w;
        __syncthreads();   // smax/ssum reuse
    }

    const float c = 1.0f / 16.0f;
    float4* mrow = (float4*)(outMean + (size_t)bt * S_LEN);
    mrow[tid] = make_float4(macc0x * c, macc0y * c, macc0z * c, macc0w * c);
    mrow[tid + 256] = make_float4(macc1x * c, macc1y * c, macc1z * c, macc1w * c);
}

// ---------------------------------------------------------------------------
extern "C" void kernel_launch(void* const* d_in, const int* in_sizes, int n_in,
                              void* d_out, int out_size) {
    const float* query = (const float*)d_in[0];
    const float* key   = (const float*)d_in[1];
    const float* value = (const float*)d_in[2];
    const float* w[4]    = {(const float*)d_in[3],  (const float*)d_in[7],
                            (const float*)d_in[11], (const float*)d_in[15]};
    const float* bias[4] = {(const float*)d_in[4],  (const float*)d_in[8],
                            (const float*)d_in[12], (const float*)d_in[16]};
    const float* la[4]   = {(const float*)d_in[5],  (const float*)d_in[9],
                            (const float*)d_in[13], (const float*)d_in[17]};
    const float* lb[4]   = {(const float*)d_in[6],  (const float*)d_in[10],
                            (const float*)d_in[14], (const float*)d_in[18]};
    float* out = (float*)d_out;

    __nv_bfloat16 *p_whi, *p_wlo, *p_ihi, *p_ilo, *p_qhi, *p_qlo, *p_khi, *p_klo;
    __nv_bfloat16 *p_vthi, *p_vtlo, *p_aohi, *p_aolo, *p_phi, *p_plo;
    float *p_v, *p_attn;
    cudaGetSymbolAddress((void**)&p_whi, g_whi);
    cudaGetSymbolAddress((void**)&p_wlo, g_wlo);
    cudaGetSymbolAddress((void**)&p_ihi, g_ihi);
    cudaGetSymbolAddress((void**)&p_ilo, g_ilo);
    cudaGetSymbolAddress((void**)&p_qhi, g_qhi);
    cudaGetSymbolAddress((void**)&p_qlo, g_qlo);
    cudaGetSymbolAddress((void**)&p_khi, g_khi);
    cudaGetSymbolAddress((void**)&p_klo, g_klo);
    cudaGetSymbolAddress((void**)&p_vthi, g_vthi);
    cudaGetSymbolAddress((void**)&p_vtlo, g_vtlo);
    cudaGetSymbolAddress((void**)&p_aohi, g_aohi);
    cudaGetSymbolAddress((void**)&p_aolo, g_aolo);
    cudaGetSymbolAddress((void**)&p_phi, g_phi);
    cudaGetSymbolAddress((void**)&p_plo, g_plo);
    cudaGetSymbolAddress((void**)&p_v, g_v);
    cudaGetSymbolAddress((void**)&p_attn, g_attn);

    const size_t WSZ = (size_t)E_DIM * E_DIM;
    const size_t ISZ = (size_t)M_ROWS * E_DIM;

    // smem: 2 stages * (2*128*40 + 2*BN*40) bf16
    const int SMEM128 = 2 * (2 * 128 * 40 + 2 * 128 * 40) * 2;  // 81920
    const int SMEM64  = 2 * (2 * 128 * 40 + 2 * 64 * 40) * 2;   // 61440
    cudaFuncSetAttribute(gemm_pair<128, 0>, cudaFuncAttributeMaxDynamicSharedMemorySize, SMEM128);
    cudaFuncSetAttribute(gemm_pair<128, 1>, cudaFuncAttributeMaxDynamicSharedMemorySize, SMEM128);
    cudaFuncSetAttribute(gemm_pair<64, 1>,  cudaFuncAttributeMaxDynamicSharedMemorySize, SMEM64);

    // Fold LoRA into effective weights (pair output)
    for (int i = 0; i < 4; i++)
        weff_kernel<<<E_DIM * E_DIM / 256, 256>>>(w[i], la[i], lb[i], i);

    // Inputs -> pair
    cvt_in_kernel<<<ISZ / 4 / 256, 256>>>(query, 0);
    cvt_in_kernel<<<ISZ / 4 / 256, 256>>>(key,   1);
    cvt_in_kernel<<<ISZ / 4 / 256, 256>>>(value, 2);

    // Q/K projections (pair out), V projection (fp32 out)
    gemm_pair<128, 1><<<dim3(8, 32, 1), 256, SMEM128>>>(
        p_ihi + 0 * ISZ, p_ilo + 0 * ISZ, E_DIM, 0,
        p_whi + 0 * WSZ, p_wlo + 0 * WSZ, E_DIM, 0,
        nullptr, p_qhi, p_qlo, E_DIM, 0, bias[0], 1.0f, E_DIM);
    gemm_pair<128, 1><<<dim3(8, 32, 1), 256, SMEM128>>>(
        p_ihi + 1 * ISZ, p_ilo + 1 * ISZ, E_DIM, 0,
        p_whi + 1 * WSZ, p_wlo + 1 * WSZ, E_DIM, 0,
        nullptr, p_khi, p_klo, E_DIM, 0, bias[1], 1.0f, E_DIM);
    gemm_pair<128, 0><<<dim3(8, 32, 1), 256, SMEM128>>>(
        p_ihi + 2 * ISZ, p_ilo + 2 * ISZ, E_DIM, 0,
        p_whi + 2 * WSZ, p_wlo + 2 * WSZ, E_DIM, 0,
        p_v, nullptr, nullptr, E_DIM, 0, bias[2], 1.0f, E_DIM);

    // V^T pair
    vt_kernel<<<dim3(S_LEN / 32, HD / 32, BH), dim3(32, 8)>>>();

    // scores = 0.125 * Q K^T (fp32 out)
    gemm_pair<128, 0><<<dim3(16, 16, 32), 256, SMEM128>>>(
        p_qhi, p_qlo, 2048, 64,
        p_khi, p_klo, 2048, 64,
        p_attn, nullptr, nullptr, S_LEN, (long long)T_LEN * S_LEN, nullptr, 0.125f, HD);

    // softmax + head-mean (writes P pair + attn_w tail)
    softmax_mean_kernel<<<B_SZ * T_LEN, 256>>>(out + (size_t)T_LEN * B_SZ * E_DIM);

    // O_head = P @ V (pair out)
    gemm_pair<64, 1><<<dim3(1, 16, 32), 256, SMEM64>>>(
        p_phi, p_plo, 2048, (long long)T_LEN * S_LEN,
        p_vthi, p_vtlo, 2048, (long long)HD * S_LEN,
        nullptr, p_aohi, p_aolo, 2048, 64, nullptr, 1.0f, S_LEN);

    // Output projection -> d_out (fp32 + bias)
    gemm_pair<128, 0><<<dim3(8, 32, 1), 256, SMEM128>>>(
        p_aohi, p_aolo, E_DIM, 0,
        p_whi + 3 * WSZ, p_wlo + 3 * WSZ, E_DIM, 0,
        out, nullptr, nullptr, E_DIM, 0, bias[3], 1.0f, E_DIM);
}